// round 2
// baseline (speedup 1.0000x reference)
#include <cuda_runtime.h>

#define T_STEPS 16
#define BLK 512

using ull = unsigned long long;

union F2u { ull u; float2 f; };

__device__ __forceinline__ ull fma2(ull a, ull b, ull c) {
    ull d;
    asm("fma.rn.f32x2 %0, %1, %2, %3;" : "=l"(d) : "l"(a), "l"(b), "l"(c));
    return d;
}
__device__ __forceinline__ float hsum2(ull a, ull b) {
    F2u x, y; x.u = a; y.u = b;
    return (x.f.x + y.f.x) + (x.f.y + y.f.y);
}
__device__ __forceinline__ float hsum1(ull a) { F2u x; x.u = a; return x.f.x + x.f.y; }
__device__ __forceinline__ ull pack2(float a, float b) { F2u t; t.f = make_float2(a, b); return t.u; }

__device__ __forceinline__ float sigm(float x) {
    return __fdividef(1.0f, 1.0f + __expf(-x));
}
__device__ __forceinline__ float tanh_fast(float x) {
    float ax = fabsf(x);
    float e = __expf(-2.0f * ax);
    float t = __fdividef(1.0f - e, 1.0f + e);
    return copysignf(t, x);
}
__device__ __forceinline__ float softplus_(float x) {
    // stable: max(x,0) + log1p(exp(-|x|))
    return fmaxf(x, 0.0f) + log1pf(__expf(-fabsf(x)));
}

// shared-memory float offsets
#define OFF_WHH 0        // 12288  (192 x 64, row-major)
#define OFF_W1T 12288    // 2048   (transposed: [m*64+k])
#define OFF_WIH 14336    // 384    (192 x 2, row-major -> ull per row)
#define OFF_BIH 14720    // 192
#define OFF_BHH 14912    // 192
#define OFF_B1  15104    // 32
#define OFF_W2  15136    // 128    (32 x 4 row-major -> float4 per row)
#define OFF_B2  15264    // 4
#define WEIGHT_BYTES (15268 * 4)                 // 61072, 16B-aligned
#define SMEM_BYTES (WEIGHT_BYTES + 32 * BLK * 8) // + hbuf (ull[32][BLK]) = 192144

__global__ void __launch_bounds__(BLK)
flow_kernel(const float* __restrict__ x, const float* __restrict__ z,
            const float* __restrict__ W_ih, const float* __restrict__ W_hh,
            const float* __restrict__ b_ih, const float* __restrict__ b_hh,
            const float* __restrict__ W1, const float* __restrict__ b1,
            const float* __restrict__ W2, const float* __restrict__ b2,
            float* __restrict__ out, int Btot)
{
    extern __shared__ unsigned char smem_raw[];
    float* sw = (float*)smem_raw;
    const int tid = threadIdx.x;

    // ---- stage weights into shared ----
    for (int i = tid; i < 12288; i += BLK) sw[OFF_WHH + i] = W_hh[i];
    for (int i = tid; i < 2048; i += BLK) {         // transpose W1 (64x32) -> [m][k]
        int m = i >> 6, k = i & 63;
        sw[OFF_W1T + i] = W1[k * 32 + m];
    }
    for (int i = tid; i < 384; i += BLK) sw[OFF_WIH + i] = W_ih[i];
    for (int i = tid; i < 192; i += BLK) { sw[OFF_BIH + i] = b_ih[i]; sw[OFF_BHH + i] = b_hh[i]; }
    for (int i = tid; i < 128; i += BLK) sw[OFF_W2 + i] = W2[i];
    if (tid < 32) sw[OFF_B1 + tid] = b1[tid];
    if (tid < 4)  sw[OFF_B2 + tid] = b2[tid];
    __syncthreads();

    ull* hbuf = (ull*)(smem_raw + WEIGHT_BYTES);   // [32][BLK] per-thread h scratch

    const int b = blockIdx.x * BLK + tid;

    // h = z  (packed pairs in registers + smem scratch copy)
    ull h2[32];
    const ull* zz = (const ull*)(z + (size_t)b * 64);
    #pragma unroll
    for (int k = 0; k < 32; ++k) { h2[k] = zz[k]; hbuf[k * BLK + tid] = h2[k]; }

    const float* xb = x + (size_t)b * (T_STEPS * 2);
    float*       yb = out + (size_t)b * (T_STEPS * 2);

    const ulonglong2* whh2 = (const ulonglong2*)(sw + OFF_WHH);  // row j at j*16
    const ull*        wih2 = (const ull*)(sw + OFF_WIH);         // row j at j
    const float* bih = sw + OFF_BIH;
    const float* bhh = sw + OFF_BHH;
    const ulonglong2* w1t2 = (const ulonglong2*)(sw + OFF_W1T);  // row m at m*16
    const float4* w2v = (const float4*)(sw + OFF_W2);
    const float* b1s = sw + OFF_B1;
    const float* b2s = sw + OFF_B2;
    const float bb20 = b2s[0], bb21 = b2s[1], bb22 = b2s[2], bb23 = b2s[3];

    float yp0 = 0.f, yp1 = 0.f;     // y_{t-1}
    float p0 = 1.f, p1 = 1.f;       // running scale products

    #pragma unroll 1
    for (int t = 0; t < T_STEPS; ++t) {
        ull y2 = pack2(yp0, yp1);

        // ---- GRU: gh = h @ W_hh^T + b_hh, fused with gates ----
        #pragma unroll 2
        for (int j = 0; j < 64; ++j) {
            const ulonglong2* wr = whh2 + j * 16;
            const ulonglong2* wzp = wr + 1024;   // row 64+j
            const ulonglong2* wn = wr + 2048;    // row 128+j
            ull ar0 = 0, ar1 = 0, az0 = 0, az1 = 0, an0 = 0, an1 = 0;
            #pragma unroll
            for (int kk = 0; kk < 16; ++kk) {
                ulonglong2 wa = wr[kk];
                ar0 = fma2(h2[2 * kk], wa.x, ar0); ar1 = fma2(h2[2 * kk + 1], wa.y, ar1);
                ulonglong2 wb = wzp[kk];
                az0 = fma2(h2[2 * kk], wb.x, az0); az1 = fma2(h2[2 * kk + 1], wb.y, az1);
                ulonglong2 wc = wn[kk];
                an0 = fma2(h2[2 * kk], wc.x, an0); an1 = fma2(h2[2 * kk + 1], wc.y, an1);
            }
            float hr = hsum2(ar0, ar1) + bhh[j];
            float hz = hsum2(az0, az1) + bhh[64 + j];
            float hn = hsum2(an0, an1) + bhh[128 + j];
            float gr = hsum1(fma2(y2, wih2[j],       0ULL)) + bih[j];
            float gz = hsum1(fma2(y2, wih2[64 + j],  0ULL)) + bih[64 + j];
            float gn = hsum1(fma2(y2, wih2[128 + j], 0ULL)) + bih[128 + j];
            float r = sigm(gr + hr);
            float u = sigm(gz + hz);
            float n = tanh_fast(gn + r * hn);
            // in-place h update in smem scratch (slot j only touched at iter j)
            float* hs = (float*)(hbuf + (j >> 1) * BLK + tid);
            float hold = hs[j & 1];
            hs[j & 1] = n + u * (hold - n);
        }

        // reload h (now h_new) into registers
        #pragma unroll
        for (int k = 0; k < 32; ++k) h2[k] = hbuf[k * BLK + tid];

        // ---- MLP: ls = relu(h@W1 + b1) @ W2 + b2, hid accumulated on the fly ----
        float ls0 = bb20, ls1 = bb21, ls2 = bb22, ls3 = bb23;
        #pragma unroll 2
        for (int m = 0; m < 32; ++m) {
            const ulonglong2* wm = w1t2 + m * 16;
            ull a0 = 0, a1 = 0;
            #pragma unroll
            for (int kk = 0; kk < 16; ++kk) {
                ulonglong2 w = wm[kk];
                a0 = fma2(h2[2 * kk], w.x, a0);
                a1 = fma2(h2[2 * kk + 1], w.y, a1);
            }
            float hid = fmaxf(hsum2(a0, a1) + b1s[m], 0.0f);
            float4 wv = w2v[m];
            ls0 = fmaf(hid, wv.x, ls0);
            ls1 = fmaf(hid, wv.y, ls1);
            ls2 = fmaf(hid, wv.z, ls2);
            ls3 = fmaf(hid, wv.w, ls3);
        }

        float s0 = softplus_(ls2) + 0.001f;
        float s1 = softplus_(ls3) + 0.001f;
        float2 xt = ((const float2*)xb)[t];
        float y0 = yp0 + ls0 + s0 * xt.x;
        float y1 = yp1 + ls1 + s1 * xt.y;
        ((float2*)yb)[t] = make_float2(y0, y1);
        p0 *= s0; p1 *= s1;
        yp0 = y0; yp1 = y1;
    }

    // logabsdet (match reference: log|prod over T| summed over D)
    out[(size_t)Btot * (T_STEPS * 2) + b] = logf(fabsf(p0)) + logf(fabsf(p1));
}

extern "C" void kernel_launch(void* const* d_in, const int* in_sizes, int n_in,
                              void* d_out, int out_size)
{
    const float* x    = (const float*)d_in[0];
    const float* z    = (const float*)d_in[1];
    const float* W_ih = (const float*)d_in[2];
    const float* W_hh = (const float*)d_in[3];
    const float* b_ih = (const float*)d_in[4];
    const float* b_hh = (const float*)d_in[5];
    const float* W1   = (const float*)d_in[6];
    const float* b1   = (const float*)d_in[7];
    const float* W2   = (const float*)d_in[8];
    const float* b2   = (const float*)d_in[9];

    int B = in_sizes[1] / 64;   // z is (B, 64)

    cudaFuncSetAttribute(flow_kernel, cudaFuncAttributeMaxDynamicSharedMemorySize, SMEM_BYTES);

    flow_kernel<<<B / BLK, BLK, SMEM_BYTES>>>(
        x, z, W_ih, W_hh, b_ih, b_hh, W1, b1, W2, b2, (float*)d_out, B);
}